// round 12
// baseline (speedup 1.0000x reference)
#include <cuda_runtime.h>
#include <cuda_fp16.h>
#include <math.h>
#include <stdint.h>

#define NN 50000
#define EE 800000
#define HF 128          // H*F = 2*64
#define INF_ 128        // IN_FEATS
#define SCAN_B 512
#define NBLK ((NN + SCAN_B - 1) / SCAN_B)   // 98

// ---------------- scratch (static device globals; no allocation) ----------------
__device__ __half g_zh[2u * NN * HF];    // half-precision z (messages), 25.6 MB
__device__ float4 g_el4[NN];             // (g0h0, g0h1, g1h0, g1h1)
__device__ float4 g_er4[NN];
__device__ int    g_csr_src[EE];
__device__ int    g_offsets[NN + 1];     // starts; mutated by scatter into ends
__device__ int    g_counts[NN];
__device__ int    g_blocksum[NBLK];
__device__ int    g_scan_done = 0;

// ---------------- host-side stream/event resources (no device memory) ----------------
struct HostRes {
    cudaStream_t s2;
    cudaEvent_t evFork, evJoin;
    HostRes() {
        cudaStreamCreateWithFlags(&s2, cudaStreamNonBlocking);
        cudaEventCreateWithFlags(&evFork, cudaEventDisableTiming);
        cudaEventCreateWithFlags(&evJoin, cudaEventDisableTiming);
    }
};
static HostRes g_res;

// ---------------- CSR build ----------------
__global__ void zero_kernel() {
    int i = blockIdx.x * blockDim.x + threadIdx.x;
    if (i < NN) g_counts[i] = 0;
}

__global__ void count_kernel(const int* __restrict__ dst) {
    int e = blockIdx.x * blockDim.x + threadIdx.x;
    if (e < EE) atomicAdd(&g_counts[dst[e]], 1);
}

// fused scan stage 1+2: per-block sums; LAST block scans the 98 block sums.
__global__ void scan12_kernel() {
    __shared__ int wsum[16];
    __shared__ int ws2[4];
    __shared__ int is_last;
    int b = blockIdx.x, t = threadIdx.x;
    int lane = t & 31, w = t >> 5;
    int i = b * SCAN_B + t;
    int v = (i < NN) ? g_counts[i] : 0;
    #pragma unroll
    for (int off = 16; off; off >>= 1) v += __shfl_xor_sync(0xffffffffu, v, off);
    if (lane == 0) wsum[w] = v;
    __syncthreads();
    if (t == 0) {
        int s = 0;
        #pragma unroll
        for (int k = 0; k < 16; k++) s += wsum[k];
        g_blocksum[b] = s;
        __threadfence();
        int prev = atomicAdd(&g_scan_done, 1);
        is_last = (prev == gridDim.x - 1);
    }
    __syncthreads();
    if (is_last) {
        int ss = 0, vv = 0;
        if (t < 128) {
            int lane2 = t & 31, w2 = t >> 5;
            vv = (t < NBLK) ? g_blocksum[t] : 0;
            ss = vv;
            #pragma unroll
            for (int off = 1; off < 32; off <<= 1) {
                int tmp = __shfl_up_sync(0xffffffffu, ss, off);
                if (lane2 >= off) ss += tmp;
            }
            if (lane2 == 31) ws2[w2] = ss;
        }
        __syncthreads();
        if (t == 0) {
            int a = 0;
            #pragma unroll
            for (int k = 0; k < 4; k++) { int tmp = ws2[k]; ws2[k] = a; a += tmp; }
            g_scan_done = 0;   // reset for next invocation (determinism)
        }
        __syncthreads();
        if (t < 128 && t < NBLK) g_blocksum[t] = ss + ws2[t >> 5] - vv;  // exclusive base
    }
}

// scan stage 3: per-block inclusive scan + block base -> start offsets
__global__ void scan3_kernel() {
    __shared__ int wsum[16];
    int b = blockIdx.x, t = threadIdx.x;
    int lane = t & 31, w = t >> 5;
    int i = b * SCAN_B + t;
    int v = (i < NN) ? g_counts[i] : 0;
    int s = v;
    #pragma unroll
    for (int off = 1; off < 32; off <<= 1) {
        int tmp = __shfl_up_sync(0xffffffffu, s, off);
        if (lane >= off) s += tmp;
    }
    if (lane == 31) wsum[w] = s;
    __syncthreads();
    if (w == 0 && lane < 16) {
        int ws_ = wsum[lane];
        #pragma unroll
        for (int off = 1; off < 16; off <<= 1) {
            int tmp = __shfl_up_sync(0x0000ffffu, ws_, off);
            if (lane >= off) ws_ += tmp;
        }
        wsum[lane] = ws_;
    }
    __syncthreads();
    int prefix = (w > 0) ? wsum[w - 1] : 0;
    int incl = s + prefix + g_blocksum[b];
    if (i < NN) g_offsets[i + 1] = incl;     // offsets[j] = start of node j
    if (b == 0 && t == 0) g_offsets[0] = 0;
}

// scatter uses offsets themselves as cursors: post-scatter offsets[d] = end_d.
__global__ void scatter_kernel(const int* __restrict__ src, const int* __restrict__ dst) {
    int e = blockIdx.x * blockDim.x + threadIdx.x;
    if (e < EE) {
        int d = dst[e];
        int p = atomicAdd(&g_offsets[d], 1);
        g_csr_src[p] = src[e];
    }
}

// ---------------- tf32 tensor-core GEMM + fused el/er + half-z store ----------------
__device__ __forceinline__ float to_tf32(float x) {
    uint32_t u;
    asm("cvt.rna.tf32.f32 %0, %1;" : "=r"(u) : "f"(x));
    return __uint_as_float(u);
}

__device__ __forceinline__ void mma_tf32(float c[4], const uint32_t a[4], const uint32_t b[2]) {
    asm volatile(
        "mma.sync.aligned.m16n8k8.row.col.f32.tf32.tf32.f32 "
        "{%0,%1,%2,%3}, {%4,%5,%6,%7}, {%8,%9}, {%0,%1,%2,%3};"
        : "+f"(c[0]), "+f"(c[1]), "+f"(c[2]), "+f"(c[3])
        : "r"(a[0]), "r"(a[1]), "r"(a[2]), "r"(a[3]), "r"(b[0]), "r"(b[1]));
}

// BM=128, BN=128, BK=32, 256 threads = 8 warps (4 m x 2 n). Warp tile 32x64.
__global__ void __launch_bounds__(256)
gemm_kernel(const float* __restrict__ x, const float* __restrict__ W,
            const float* __restrict__ attn_l, const float* __restrict__ attn_r) {
    __shared__ float As[128][36];
    __shared__ float Bs[128][36];

    const int g = blockIdx.y;                       // 0 -> W[1] (u), 1 -> W[2] (c)
    const float* Wg = W + (size_t)(g + 1) * HF * INF_;
    const int row0 = blockIdx.x * 128;
    const int t = threadIdx.x;
    const int lane = t & 31, wid = t >> 5;
    const int warp_m = wid >> 1, warp_n = wid & 1;

    float c[2][8][4];
    #pragma unroll
    for (int mi = 0; mi < 2; mi++)
        #pragma unroll
        for (int ni = 0; ni < 8; ni++)
            #pragma unroll
            for (int q = 0; q < 4; q++) c[mi][ni][q] = 0.0f;

    for (int k0 = 0; k0 < INF_; k0 += 32) {
        #pragma unroll
        for (int r = 0; r < 4; r++) {
            int id = t + 256 * r;
            int row = id >> 3;
            int kv = (id & 7) << 2;
            float4 v = make_float4(0.f, 0.f, 0.f, 0.f);
            int gr = row0 + row;
            if (gr < NN) v = *(const float4*)(x + (size_t)gr * INF_ + k0 + kv);
            As[row][kv + 0] = to_tf32(v.x);
            As[row][kv + 1] = to_tf32(v.y);
            As[row][kv + 2] = to_tf32(v.z);
            As[row][kv + 3] = to_tf32(v.w);
            float4 w4 = *(const float4*)(Wg + row * INF_ + k0 + kv);
            Bs[row][kv + 0] = to_tf32(w4.x);
            Bs[row][kv + 1] = to_tf32(w4.y);
            Bs[row][kv + 2] = to_tf32(w4.z);
            Bs[row][kv + 3] = to_tf32(w4.w);
        }
        __syncthreads();

        #pragma unroll
        for (int kk = 0; kk < 32; kk += 8) {
            uint32_t af[2][4], bf[8][2];
            const int ac = kk + (lane & 3);
            #pragma unroll
            for (int mi = 0; mi < 2; mi++) {
                int ar = warp_m * 32 + mi * 16 + (lane >> 2);
                af[mi][0] = __float_as_uint(As[ar][ac]);
                af[mi][1] = __float_as_uint(As[ar + 8][ac]);
                af[mi][2] = __float_as_uint(As[ar][ac + 4]);
                af[mi][3] = __float_as_uint(As[ar + 8][ac + 4]);
            }
            #pragma unroll
            for (int ni = 0; ni < 8; ni++) {
                int br = warp_n * 64 + ni * 8 + (lane >> 2);
                bf[ni][0] = __float_as_uint(Bs[br][ac]);
                bf[ni][1] = __float_as_uint(Bs[br][ac + 4]);
            }
            #pragma unroll
            for (int mi = 0; mi < 2; mi++)
                #pragma unroll
                for (int ni = 0; ni < 8; ni++)
                    mma_tf32(c[mi][ni], af[mi], bf[ni]);
        }
        __syncthreads();
    }

    // epilogue: store half z + compute el/er (head = warp_n) via quad reduction
    const float* al = attn_l + (g + 1) * HF;
    const float* ar = attn_r + (g + 1) * HF;
    #pragma unroll
    for (int mi = 0; mi < 2; mi++) {
        #pragma unroll
        for (int half = 0; half < 2; half++) {
            int rr = row0 + warp_m * 32 + mi * 16 + (lane >> 2) + half * 8;
            float elp = 0.f, erp = 0.f;
            if (rr < NN) {
                __half* zp = g_zh + ((size_t)g * NN + rr) * HF;
                #pragma unroll
                for (int ni = 0; ni < 8; ni++) {
                    int cc = warp_n * 64 + ni * 8 + (lane & 3) * 2;
                    float cx = half ? c[mi][ni][2] : c[mi][ni][0];
                    float cy = half ? c[mi][ni][3] : c[mi][ni][1];
                    *(half2*)(zp + cc) = __floats2half2_rn(cx, cy);
                    elp = fmaf(cx, __ldg(al + cc), fmaf(cy, __ldg(al + cc + 1), elp));
                    erp = fmaf(cx, __ldg(ar + cc), fmaf(cy, __ldg(ar + cc + 1), erp));
                }
            }
            elp += __shfl_xor_sync(0xffffffffu, elp, 1);
            elp += __shfl_xor_sync(0xffffffffu, elp, 2);
            erp += __shfl_xor_sync(0xffffffffu, erp, 1);
            erp += __shfl_xor_sync(0xffffffffu, erp, 2);
            if ((lane & 3) == 0 && rr < NN) {
                ((float*)g_el4)[(size_t)rr * 4 + g * 2 + warp_n] = elp;
                ((float*)g_er4)[(size_t)rr * 4 + g * 2 + warp_n] = erp;
            }
        }
    }
}

// ---------------- packed f32x2 FMA (FFMA2 — only reachable via PTX) ----------------
__device__ __forceinline__ float2 fma2(float2 a, float2 b, float2 c) {
    float2 d;
    asm("fma.rn.f32x2 %0, %1, %2, %3;"
        : "=l"(reinterpret_cast<unsigned long long&>(d))
        : "l"(reinterpret_cast<unsigned long long&>(a)),
          "l"(reinterpret_cast<unsigned long long&>(b)),
          "l"(reinterpret_cast<unsigned long long&>(c)));
    return d;
}

// ---------------- fused edge softmax-aggregate + sigmoid combine ----------------
// One warp per node, both gates. Online softmax (leaky_relu monotonic => exact).
// Post-scatter offsets: start = offsets[n-1] (0 for n=0), end = offsets[n].
// Lane L owns cols [4L, 4L+4); lanes 0-15 = head0, 16-31 = head1.
__global__ void __launch_bounds__(256)
edge_final_kernel(const float* __restrict__ h,
                  const float* __restrict__ conv_bias,
                  const float* __restrict__ gate_bias,
                  float* __restrict__ out) {
    int n = (blockIdx.x * blockDim.x + threadIdx.x) >> 5;
    if (n >= NN) return;
    int lane = threadIdx.x & 31;
    int hf = lane * 4;

    float4 cbu = *(const float4*)(conv_bias + HF + hf);
    float4 gbu = *(const float4*)(gate_bias + HF + hf);
    float4 cbc = *(const float4*)(conv_bias + 2 * HF + hf);
    float4 gbc = *(const float4*)(gate_bias + 2 * HF + hf);
    float bu0 = cbu.x + gbu.x, bu1 = cbu.y + gbu.y, bu2 = cbu.z + gbu.z, bu3 = cbu.w + gbu.w;
    float bc0 = cbc.x + gbc.x, bc1 = cbc.y + gbc.y, bc2 = cbc.z + gbc.z, bc3 = cbc.w + gbc.w;

    int end = g_offsets[n];
    int start = (n == 0) ? 0 : g_offsets[n - 1];

    float2 A0 = make_float2(0.f, 0.f), A1 = make_float2(0.f, 0.f);  // gate u
    float2 B0 = make_float2(0.f, 0.f), B1 = make_float2(0.f, 0.f);  // gate c
    float s0 = 0.f, s1 = 0.f, s2 = 0.f, s3 = 0.f;

    if (start < end) {
        float4 ern = g_el4[0].x == g_el4[0].x ? g_er4[n] : g_er4[n];  // plain load
        ern = g_er4[n];
        float m0 = -1e30f, m1 = -1e30f, m2 = -1e30f, m3 = -1e30f;
        for (int base = start; base < end; base += 32) {
            int i = base + lane;
            int sid = 0;
            float e0 = -1e30f, e1 = -1e30f, e2 = -1e30f, e3 = -1e30f;
            if (i < end) {
                sid = g_csr_src[i];
                float4 els = g_el4[sid];
                e0 = els.x + ern.x; e0 = (e0 > 0.f) ? e0 : 0.2f * e0;
                e1 = els.y + ern.y; e1 = (e1 > 0.f) ? e1 : 0.2f * e1;
                e2 = els.z + ern.z; e2 = (e2 > 0.f) ? e2 : 0.2f * e2;
                e3 = els.w + ern.w; e3 = (e3 > 0.f) ? e3 : 0.2f * e3;
            }
            // batch max per component
            float b0 = e0, b1 = e1, b2 = e2, b3 = e3;
            #pragma unroll
            for (int off = 16; off; off >>= 1) {
                b0 = fmaxf(b0, __shfl_xor_sync(0xffffffffu, b0, off));
                b1 = fmaxf(b1, __shfl_xor_sync(0xffffffffu, b1, off));
                b2 = fmaxf(b2, __shfl_xor_sync(0xffffffffu, b2, off));
                b3 = fmaxf(b3, __shfl_xor_sync(0xffffffffu, b3, off));
            }
            float n0 = fmaxf(m0, b0), n1 = fmaxf(m1, b1);
            float n2 = fmaxf(m2, b2), n3 = fmaxf(m3, b3);
            float sc0 = __expf(m0 - n0), sc1 = __expf(m1 - n1);
            float sc2 = __expf(m2 - n2), sc3 = __expf(m3 - n3);
            float scA = (lane < 16) ? sc0 : sc1;
            float scB = (lane < 16) ? sc2 : sc3;
            A0.x *= scA; A0.y *= scA; A1.x *= scA; A1.y *= scA;
            B0.x *= scB; B0.y *= scB; B1.x *= scB; B1.y *= scB;
            s0 *= sc0; s1 *= sc1; s2 *= sc2; s3 *= sc3;
            m0 = n0; m1 = n1; m2 = n2; m3 = n3;

            float w0 = __expf(e0 - m0), w1 = __expf(e1 - m1);
            float w2 = __expf(e2 - m2), w3 = __expf(e3 - m3);   // OOB lanes: exp(-huge)=0

            int cnt = min(32, end - base);
            #pragma unroll 2
            for (int j = 0; j < cnt; j++) {
                int   sj  = __shfl_sync(0xffffffffu, sid, j);
                float wj0 = __shfl_sync(0xffffffffu, w0, j);
                float wj1 = __shfl_sync(0xffffffffu, w1, j);
                float wj2 = __shfl_sync(0xffffffffu, w2, j);
                float wj3 = __shfl_sync(0xffffffffu, w3, j);
                const uint2* z0 = (const uint2*)(g_zh + (size_t)sj * HF);
                const uint2* z1 = (const uint2*)(g_zh + ((size_t)NN + sj) * HF);
                uint2 q0 = z0[lane], q1 = z1[lane];
                float2 f00 = __half22float2(*(half2*)&q0.x);
                float2 f01 = __half22float2(*(half2*)&q0.y);
                float2 f10 = __half22float2(*(half2*)&q1.x);
                float2 f11 = __half22float2(*(half2*)&q1.y);
                float wA = (lane < 16) ? wj0 : wj1;
                float wB = (lane < 16) ? wj2 : wj3;
                float2 wA2 = make_float2(wA, wA);
                float2 wB2 = make_float2(wB, wB);
                A0 = fma2(wA2, f00, A0);
                A1 = fma2(wA2, f01, A1);
                B0 = fma2(wB2, f10, B0);
                B1 = fma2(wB2, f11, B1);
                s0 += wj0; s1 += wj1; s2 += wj2; s3 += wj3;
            }
        }
        float invA = 1.0f / ((lane < 16) ? s0 : s1);
        float invB = 1.0f / ((lane < 16) ? s2 : s3);
        A0.x *= invA; A0.y *= invA; A1.x *= invA; A1.y *= invA;
        B0.x *= invB; B0.y *= invB; B1.x *= invB; B1.y *= invB;
    }

    float4 hv = *(const float4*)(h + (size_t)n * HF + hf);
    float u0 = 1.0f / (1.0f + __expf(-(A0.x + bu0)));
    float u1 = 1.0f / (1.0f + __expf(-(A0.y + bu1)));
    float u2 = 1.0f / (1.0f + __expf(-(A1.x + bu2)));
    float u3 = 1.0f / (1.0f + __expf(-(A1.y + bu3)));
    float c0 = 1.0f / (1.0f + __expf(-(B0.x + bc0)));
    float c1 = 1.0f / (1.0f + __expf(-(B0.y + bc1)));
    float c2 = 1.0f / (1.0f + __expf(-(B1.x + bc2)));
    float c3 = 1.0f / (1.0f + __expf(-(B1.y + bc3)));
    float4 o;
    o.x = u0 * hv.x + (1.0f - u0) * c0;
    o.y = u1 * hv.y + (1.0f - u1) * c1;
    o.z = u2 * hv.z + (1.0f - u2) * c2;
    o.w = u3 * hv.w + (1.0f - u3) * c3;
    *(float4*)(out + (size_t)n * HF + hf) = o;
}

// ---------------- launch: CSR chain on s2 ∥ GEMM on capture stream ----------------
extern "C" void kernel_launch(void* const* d_in, const int* in_sizes, int n_in,
                              void* d_out, int out_size) {
    const float* x         = (const float*)d_in[0];
    const float* h         = (const float*)d_in[1];
    const float* W         = (const float*)d_in[2];
    const float* attn_l    = (const float*)d_in[3];
    const float* attn_r    = (const float*)d_in[4];
    const float* conv_bias = (const float*)d_in[5];
    const float* gate_bias = (const float*)d_in[6];
    const int*   src       = (const int*)d_in[7];
    const int*   dst       = (const int*)d_in[8];
    float* out = (float*)d_out;

    cudaStream_t s2 = g_res.s2;

    // fork: CSR build on s2
    cudaEventRecord(g_res.evFork, 0);
    cudaStreamWaitEvent(s2, g_res.evFork, 0);

    zero_kernel<<<(NN + 255) / 256, 256, 0, s2>>>();
    count_kernel<<<(EE + 511) / 512, 512, 0, s2>>>(dst);
    scan12_kernel<<<NBLK, SCAN_B, 0, s2>>>();
    scan3_kernel<<<NBLK, SCAN_B, 0, s2>>>();
    scatter_kernel<<<(EE + 511) / 512, 512, 0, s2>>>(src, dst);

    // GEMM (+ fused el/er) on the capture stream, concurrent with CSR build
    gemm_kernel<<<dim3((NN + 127) / 128, 2), 256>>>(x, W, attn_l, attn_r);

    // join: edge_final needs both
    cudaEventRecord(g_res.evJoin, s2);
    cudaStreamWaitEvent(0, g_res.evJoin, 0);

    edge_final_kernel<<<(NN * 32 + 255) / 256, 256>>>(h, conv_bias, gate_bias, out);
}

// round 13
// speedup vs baseline: 1.0337x; 1.0337x over previous
#include <cuda_runtime.h>
#include <cuda_fp16.h>
#include <math.h>
#include <stdint.h>

#define NN 50000
#define EE 800000
#define HF 128          // H*F = 2*64
#define INF_ 128        // IN_FEATS
#define SCAN_B 512
#define NBLK ((NN + SCAN_B - 1) / SCAN_B)   // 98

// ---------------- scratch (static device globals; no allocation) ----------------
__device__ __half g_zh[2u * NN * HF];    // half-precision z (messages), 25.6 MB
__device__ float4 g_el4[NN];             // (g0h0, g0h1, g1h0, g1h1)
__device__ float4 g_er4[NN];
__device__ int    g_csr_src[EE];
__device__ int    g_offsets[NN + 1];     // starts; mutated by scatter into ends
__device__ int    g_counts[NN];
__device__ int    g_blocksum[NBLK];
__device__ int    g_scan_done = 0;

// ---------------- CSR build ----------------
__global__ void zero_kernel() {
    int i = blockIdx.x * blockDim.x + threadIdx.x;
    if (i < NN) g_counts[i] = 0;
}

__global__ void count_kernel(const int* __restrict__ dst) {
    int e = blockIdx.x * blockDim.x + threadIdx.x;
    if (e < EE) atomicAdd(&g_counts[dst[e]], 1);
}

// fused scan stage 1+2: per-block sums; LAST block scans the 98 block sums.
__global__ void scan12_kernel() {
    __shared__ int wsum[16];
    __shared__ int ws2[4];
    __shared__ int is_last;
    int b = blockIdx.x, t = threadIdx.x;
    int lane = t & 31, w = t >> 5;
    int i = b * SCAN_B + t;
    int v = (i < NN) ? g_counts[i] : 0;
    #pragma unroll
    for (int off = 16; off; off >>= 1) v += __shfl_xor_sync(0xffffffffu, v, off);
    if (lane == 0) wsum[w] = v;
    __syncthreads();
    if (t == 0) {
        int s = 0;
        #pragma unroll
        for (int k = 0; k < 16; k++) s += wsum[k];
        g_blocksum[b] = s;
        __threadfence();
        int prev = atomicAdd(&g_scan_done, 1);
        is_last = (prev == gridDim.x - 1);
    }
    __syncthreads();
    if (is_last) {
        int ss = 0, vv = 0;
        if (t < 128) {
            int lane2 = t & 31, w2 = t >> 5;
            vv = (t < NBLK) ? g_blocksum[t] : 0;
            ss = vv;
            #pragma unroll
            for (int off = 1; off < 32; off <<= 1) {
                int tmp = __shfl_up_sync(0xffffffffu, ss, off);
                if (lane2 >= off) ss += tmp;
            }
            if (lane2 == 31) ws2[w2] = ss;
        }
        __syncthreads();
        if (t == 0) {
            int a = 0;
            #pragma unroll
            for (int k = 0; k < 4; k++) { int tmp = ws2[k]; ws2[k] = a; a += tmp; }
            g_scan_done = 0;   // reset for next invocation (determinism)
        }
        __syncthreads();
        if (t < 128 && t < NBLK) g_blocksum[t] = ss + ws2[t >> 5] - vv;  // exclusive base
    }
}

// scan stage 3: per-block inclusive scan + block base -> start offsets
__global__ void scan3_kernel() {
    __shared__ int wsum[16];
    int b = blockIdx.x, t = threadIdx.x;
    int lane = t & 31, w = t >> 5;
    int i = b * SCAN_B + t;
    int v = (i < NN) ? g_counts[i] : 0;
    int s = v;
    #pragma unroll
    for (int off = 1; off < 32; off <<= 1) {
        int tmp = __shfl_up_sync(0xffffffffu, s, off);
        if (lane >= off) s += tmp;
    }
    if (lane == 31) wsum[w] = s;
    __syncthreads();
    if (w == 0 && lane < 16) {
        int ws_ = wsum[lane];
        #pragma unroll
        for (int off = 1; off < 16; off <<= 1) {
            int tmp = __shfl_up_sync(0x0000ffffu, ws_, off);
            if (lane >= off) ws_ += tmp;
        }
        wsum[lane] = ws_;
    }
    __syncthreads();
    int prefix = (w > 0) ? wsum[w - 1] : 0;
    int incl = s + prefix + g_blocksum[b];
    if (i < NN) g_offsets[i + 1] = incl;     // offsets[j] = start of node j
    if (b == 0 && t == 0) g_offsets[0] = 0;
}

// scatter uses offsets themselves as cursors: post-scatter offsets[d] = end_d.
__global__ void scatter_kernel(const int* __restrict__ src, const int* __restrict__ dst) {
    int e = blockIdx.x * blockDim.x + threadIdx.x;
    if (e < EE) {
        int d = dst[e];
        int p = atomicAdd(&g_offsets[d], 1);
        g_csr_src[p] = src[e];
    }
}

// ---------------- tf32 tensor-core GEMM + fused el/er + half-z store ----------------
__device__ __forceinline__ float to_tf32(float x) {
    uint32_t u;
    asm("cvt.rna.tf32.f32 %0, %1;" : "=r"(u) : "f"(x));
    return __uint_as_float(u);
}

__device__ __forceinline__ void mma_tf32(float c[4], const uint32_t a[4], const uint32_t b[2]) {
    asm volatile(
        "mma.sync.aligned.m16n8k8.row.col.f32.tf32.tf32.f32 "
        "{%0,%1,%2,%3}, {%4,%5,%6,%7}, {%8,%9}, {%0,%1,%2,%3};"
        : "+f"(c[0]), "+f"(c[1]), "+f"(c[2]), "+f"(c[3])
        : "r"(a[0]), "r"(a[1]), "r"(a[2]), "r"(a[3]), "r"(b[0]), "r"(b[1]));
}

// BM=128, BN=128, BK=32, 256 threads = 8 warps (4 m x 2 n). Warp tile 32x64.
__global__ void __launch_bounds__(256)
gemm_kernel(const float* __restrict__ x, const float* __restrict__ W,
            const float* __restrict__ attn_l, const float* __restrict__ attn_r) {
    __shared__ float As[128][36];
    __shared__ float Bs[128][36];

    const int g = blockIdx.y;                       // 0 -> W[1] (u), 1 -> W[2] (c)
    const float* Wg = W + (size_t)(g + 1) * HF * INF_;
    const int row0 = blockIdx.x * 128;
    const int t = threadIdx.x;
    const int lane = t & 31, wid = t >> 5;
    const int warp_m = wid >> 1, warp_n = wid & 1;

    float c[2][8][4];
    #pragma unroll
    for (int mi = 0; mi < 2; mi++)
        #pragma unroll
        for (int ni = 0; ni < 8; ni++)
            #pragma unroll
            for (int q = 0; q < 4; q++) c[mi][ni][q] = 0.0f;

    for (int k0 = 0; k0 < INF_; k0 += 32) {
        #pragma unroll
        for (int r = 0; r < 4; r++) {
            int id = t + 256 * r;
            int row = id >> 3;
            int kv = (id & 7) << 2;
            float4 v = make_float4(0.f, 0.f, 0.f, 0.f);
            int gr = row0 + row;
            if (gr < NN) v = *(const float4*)(x + (size_t)gr * INF_ + k0 + kv);
            As[row][kv + 0] = to_tf32(v.x);
            As[row][kv + 1] = to_tf32(v.y);
            As[row][kv + 2] = to_tf32(v.z);
            As[row][kv + 3] = to_tf32(v.w);
            float4 w4 = *(const float4*)(Wg + row * INF_ + k0 + kv);
            Bs[row][kv + 0] = to_tf32(w4.x);
            Bs[row][kv + 1] = to_tf32(w4.y);
            Bs[row][kv + 2] = to_tf32(w4.z);
            Bs[row][kv + 3] = to_tf32(w4.w);
        }
        __syncthreads();

        #pragma unroll
        for (int kk = 0; kk < 32; kk += 8) {
            uint32_t af[2][4], bf[8][2];
            const int ac = kk + (lane & 3);
            #pragma unroll
            for (int mi = 0; mi < 2; mi++) {
                int ar = warp_m * 32 + mi * 16 + (lane >> 2);
                af[mi][0] = __float_as_uint(As[ar][ac]);
                af[mi][1] = __float_as_uint(As[ar + 8][ac]);
                af[mi][2] = __float_as_uint(As[ar][ac + 4]);
                af[mi][3] = __float_as_uint(As[ar + 8][ac + 4]);
            }
            #pragma unroll
            for (int ni = 0; ni < 8; ni++) {
                int br = warp_n * 64 + ni * 8 + (lane >> 2);
                bf[ni][0] = __float_as_uint(Bs[br][ac]);
                bf[ni][1] = __float_as_uint(Bs[br][ac + 4]);
            }
            #pragma unroll
            for (int mi = 0; mi < 2; mi++)
                #pragma unroll
                for (int ni = 0; ni < 8; ni++)
                    mma_tf32(c[mi][ni], af[mi], bf[ni]);
        }
        __syncthreads();
    }

    // epilogue: store half z + compute el/er (head = warp_n) via quad reduction
    const float* al = attn_l + (g + 1) * HF;
    const float* ar = attn_r + (g + 1) * HF;
    #pragma unroll
    for (int mi = 0; mi < 2; mi++) {
        #pragma unroll
        for (int half = 0; half < 2; half++) {
            int rr = row0 + warp_m * 32 + mi * 16 + (lane >> 2) + half * 8;
            float elp = 0.f, erp = 0.f;
            if (rr < NN) {
                __half* zp = g_zh + ((size_t)g * NN + rr) * HF;
                #pragma unroll
                for (int ni = 0; ni < 8; ni++) {
                    int cc = warp_n * 64 + ni * 8 + (lane & 3) * 2;
                    float cx = half ? c[mi][ni][2] : c[mi][ni][0];
                    float cy = half ? c[mi][ni][3] : c[mi][ni][1];
                    *(half2*)(zp + cc) = __floats2half2_rn(cx, cy);
                    elp = fmaf(cx, __ldg(al + cc), fmaf(cy, __ldg(al + cc + 1), elp));
                    erp = fmaf(cx, __ldg(ar + cc), fmaf(cy, __ldg(ar + cc + 1), erp));
                }
            }
            elp += __shfl_xor_sync(0xffffffffu, elp, 1);
            elp += __shfl_xor_sync(0xffffffffu, elp, 2);
            erp += __shfl_xor_sync(0xffffffffu, erp, 1);
            erp += __shfl_xor_sync(0xffffffffu, erp, 2);
            if ((lane & 3) == 0 && rr < NN) {
                ((float*)g_el4)[(size_t)rr * 4 + g * 2 + warp_n] = elp;
                ((float*)g_er4)[(size_t)rr * 4 + g * 2 + warp_n] = erp;
            }
        }
    }
}

// ---------------- fused edge softmax-aggregate + sigmoid combine ----------------
// One warp per node, both gates. Online softmax (leaky_relu monotonic => exact).
// Post-scatter offsets: start = offsets[n-1] (0 for n=0), end = offsets[n].
// Lane L owns cols [4L, 4L+4); lanes 0-15 = head0, 16-31 = head1.
// Softmax denominators accumulate PER-LANE (one add per owned edge) and are
// warp-reduced once at the end — the uniform online-rescale keeps partials exact.
__global__ void __launch_bounds__(256)
edge_final_kernel(const float* __restrict__ h,
                  const float* __restrict__ conv_bias,
                  const float* __restrict__ gate_bias,
                  float* __restrict__ out) {
    int n = (blockIdx.x * blockDim.x + threadIdx.x) >> 5;
    if (n >= NN) return;
    int lane = threadIdx.x & 31;
    int hf = lane * 4;

    float4 cbu = *(const float4*)(conv_bias + HF + hf);
    float4 gbu = *(const float4*)(gate_bias + HF + hf);
    float4 cbc = *(const float4*)(conv_bias + 2 * HF + hf);
    float4 gbc = *(const float4*)(gate_bias + 2 * HF + hf);
    float bu0 = cbu.x + gbu.x, bu1 = cbu.y + gbu.y, bu2 = cbu.z + gbu.z, bu3 = cbu.w + gbu.w;
    float bc0 = cbc.x + gbc.x, bc1 = cbc.y + gbc.y, bc2 = cbc.z + gbc.z, bc3 = cbc.w + gbc.w;

    int end = g_offsets[n];
    int start = (n == 0) ? 0 : g_offsets[n - 1];

    float a00 = 0.f, a01 = 0.f, a02 = 0.f, a03 = 0.f;   // gate u (4 cols of this lane)
    float a10 = 0.f, a11 = 0.f, a12 = 0.f, a13 = 0.f;   // gate c
    float s0 = 0.f, s1 = 0.f, s2 = 0.f, s3 = 0.f;       // per-lane softmax partials

    if (start < end) {
        float4 ern = g_er4[n];
        float m0 = -1e30f, m1 = -1e30f, m2 = -1e30f, m3 = -1e30f;
        for (int base = start; base < end; base += 32) {
            int i = base + lane;
            int sid = 0;
            float e0 = -1e30f, e1 = -1e30f, e2 = -1e30f, e3 = -1e30f;
            if (i < end) {
                sid = g_csr_src[i];
                float4 els = g_el4[sid];
                e0 = els.x + ern.x; e0 = (e0 > 0.f) ? e0 : 0.2f * e0;
                e1 = els.y + ern.y; e1 = (e1 > 0.f) ? e1 : 0.2f * e1;
                e2 = els.z + ern.z; e2 = (e2 > 0.f) ? e2 : 0.2f * e2;
                e3 = els.w + ern.w; e3 = (e3 > 0.f) ? e3 : 0.2f * e3;
            }
            // batch max per component
            float b0 = e0, b1 = e1, b2 = e2, b3 = e3;
            #pragma unroll
            for (int off = 16; off; off >>= 1) {
                b0 = fmaxf(b0, __shfl_xor_sync(0xffffffffu, b0, off));
                b1 = fmaxf(b1, __shfl_xor_sync(0xffffffffu, b1, off));
                b2 = fmaxf(b2, __shfl_xor_sync(0xffffffffu, b2, off));
                b3 = fmaxf(b3, __shfl_xor_sync(0xffffffffu, b3, off));
            }
            float n0 = fmaxf(m0, b0), n1 = fmaxf(m1, b1);
            float n2 = fmaxf(m2, b2), n3 = fmaxf(m3, b3);
            float sc0 = __expf(m0 - n0), sc1 = __expf(m1 - n1);
            float sc2 = __expf(m2 - n2), sc3 = __expf(m3 - n3);
            float scA = (lane < 16) ? sc0 : sc1;
            float scB = (lane < 16) ? sc2 : sc3;
            a00 *= scA; a01 *= scA; a02 *= scA; a03 *= scA;
            a10 *= scB; a11 *= scB; a12 *= scB; a13 *= scB;
            s0 *= sc0; s1 *= sc1; s2 *= sc2; s3 *= sc3;
            m0 = n0; m1 = n1; m2 = n2; m3 = n3;

            float w0 = __expf(e0 - m0), w1 = __expf(e1 - m1);
            float w2 = __expf(e2 - m2), w3 = __expf(e3 - m3);   // OOB lanes: exp(-huge)=0
            s0 += w0; s1 += w1; s2 += w2; s3 += w3;              // per-lane, once per batch

            int cnt = min(32, end - base);
            for (int j = 0; j < cnt; j++) {
                int   sj  = __shfl_sync(0xffffffffu, sid, j);
                float wj0 = __shfl_sync(0xffffffffu, w0, j);
                float wj1 = __shfl_sync(0xffffffffu, w1, j);
                float wj2 = __shfl_sync(0xffffffffu, w2, j);
                float wj3 = __shfl_sync(0xffffffffu, w3, j);
                const uint2* z0 = (const uint2*)(g_zh + (size_t)sj * HF);
                const uint2* z1 = (const uint2*)(g_zh + ((size_t)NN + sj) * HF);
                uint2 q0 = z0[lane], q1 = z1[lane];
                float2 f00 = __half22float2(*(half2*)&q0.x);
                float2 f01 = __half22float2(*(half2*)&q0.y);
                float2 f10 = __half22float2(*(half2*)&q1.x);
                float2 f11 = __half22float2(*(half2*)&q1.y);
                float wA = (lane < 16) ? wj0 : wj1;
                float wB = (lane < 16) ? wj2 : wj3;
                a00 = fmaf(wA, f00.x, a00); a01 = fmaf(wA, f00.y, a01);
                a02 = fmaf(wA, f01.x, a02); a03 = fmaf(wA, f01.y, a03);
                a10 = fmaf(wB, f10.x, a10); a11 = fmaf(wB, f10.y, a11);
                a12 = fmaf(wB, f11.x, a12); a13 = fmaf(wB, f11.y, a13);
            }
        }
        // reduce per-lane softmax partials (rescaled identically -> exact)
        #pragma unroll
        for (int off = 16; off; off >>= 1) {
            s0 += __shfl_xor_sync(0xffffffffu, s0, off);
            s1 += __shfl_xor_sync(0xffffffffu, s1, off);
            s2 += __shfl_xor_sync(0xffffffffu, s2, off);
            s3 += __shfl_xor_sync(0xffffffffu, s3, off);
        }
        float invA = 1.0f / ((lane < 16) ? s0 : s1);
        float invB = 1.0f / ((lane < 16) ? s2 : s3);
        a00 *= invA; a01 *= invA; a02 *= invA; a03 *= invA;
        a10 *= invB; a11 *= invB; a12 *= invB; a13 *= invB;
    }

    float4 hv = *(const float4*)(h + (size_t)n * HF + hf);
    float u0 = 1.0f / (1.0f + __expf(-(a00 + bu0)));
    float u1 = 1.0f / (1.0f + __expf(-(a01 + bu1)));
    float u2 = 1.0f / (1.0f + __expf(-(a02 + bu2)));
    float u3 = 1.0f / (1.0f + __expf(-(a03 + bu3)));
    float c0 = 1.0f / (1.0f + __expf(-(a10 + bc0)));
    float c1 = 1.0f / (1.0f + __expf(-(a11 + bc1)));
    float c2 = 1.0f / (1.0f + __expf(-(a12 + bc2)));
    float c3 = 1.0f / (1.0f + __expf(-(a13 + bc3)));
    float4 o;
    o.x = u0 * hv.x + (1.0f - u0) * c0;
    o.y = u1 * hv.y + (1.0f - u1) * c1;
    o.z = u2 * hv.z + (1.0f - u2) * c2;
    o.w = u3 * hv.w + (1.0f - u3) * c3;
    *(float4*)(out + (size_t)n * HF + hf) = o;
}

// ---------------- launch (serial: R12's stream fork regressed; reverted) ----------------
extern "C" void kernel_launch(void* const* d_in, const int* in_sizes, int n_in,
                              void* d_out, int out_size) {
    const float* x         = (const float*)d_in[0];
    const float* h         = (const float*)d_in[1];
    const float* W         = (const float*)d_in[2];
    const float* attn_l    = (const float*)d_in[3];
    const float* attn_r    = (const float*)d_in[4];
    const float* conv_bias = (const float*)d_in[5];
    const float* gate_bias = (const float*)d_in[6];
    const int*   src       = (const int*)d_in[7];
    const int*   dst       = (const int*)d_in[8];
    float* out = (float*)d_out;

    zero_kernel<<<(NN + 255) / 256, 256>>>();
    count_kernel<<<(EE + 511) / 512, 512>>>(dst);
    scan12_kernel<<<NBLK, SCAN_B>>>();
    scan3_kernel<<<NBLK, SCAN_B>>>();
    scatter_kernel<<<(EE + 511) / 512, 512>>>(src, dst);

    gemm_kernel<<<dim3((NN + 127) / 128, 2), 256>>>(x, W, attn_l, attn_r);
    edge_final_kernel<<<(NN * 32 + 255) / 256, 256>>>(h, conv_bias, gate_bias, out);
}

// round 14
// speedup vs baseline: 1.0885x; 1.0531x over previous
#include <cuda_runtime.h>
#include <cuda_fp16.h>
#include <math.h>
#include <stdint.h>

#define NN 50000
#define EE 800000
#define HF 128          // H*F = 2*64
#define INF_ 128        // IN_FEATS
#define SCAN_B 512
#define NBLK ((NN + SCAN_B - 1) / SCAN_B)   // 98

// ---------------- scratch (static device globals; no allocation) ----------------
__device__ __half g_zh[2u * NN * HF];    // half-precision z (messages), 25.6 MB
__device__ float4 g_el4[NN];             // (g0h0, g0h1, g1h0, g1h1)
__device__ float4 g_er4[NN];
__device__ int    g_csr_src[EE];
__device__ int    g_offsets[NN + 1];
__device__ int    g_counts[NN];
__device__ int    g_cursor[NN];
__device__ int    g_blocksum[NBLK];
__device__ int    g_scan_done = 0;

// ---------------- CSR build ----------------
__global__ void zero_kernel() {
    int i = blockIdx.x * blockDim.x + threadIdx.x;
    if (i < NN) g_counts[i] = 0;
}

__global__ void count_kernel(const int* __restrict__ dst) {
    int e = blockIdx.x * blockDim.x + threadIdx.x;
    if (e < EE) atomicAdd(&g_counts[dst[e]], 1);
}

// fused scan stage 1+2: per-block sums; LAST block scans the 98 block sums.
__global__ void scan12_kernel() {
    __shared__ int wsum[16];
    __shared__ int ws2[4];
    __shared__ int is_last;
    int b = blockIdx.x, t = threadIdx.x;
    int lane = t & 31, w = t >> 5;
    int i = b * SCAN_B + t;
    int v = (i < NN) ? g_counts[i] : 0;
    #pragma unroll
    for (int off = 16; off; off >>= 1) v += __shfl_xor_sync(0xffffffffu, v, off);
    if (lane == 0) wsum[w] = v;
    __syncthreads();
    if (t == 0) {
        int s = 0;
        #pragma unroll
        for (int k = 0; k < 16; k++) s += wsum[k];
        g_blocksum[b] = s;
        __threadfence();
        int prev = atomicAdd(&g_scan_done, 1);
        is_last = (prev == gridDim.x - 1);
    }
    __syncthreads();
    if (is_last) {
        int ss = 0, vv = 0;
        if (t < 128) {
            int lane2 = t & 31, w2 = t >> 5;
            vv = (t < NBLK) ? g_blocksum[t] : 0;
            ss = vv;
            #pragma unroll
            for (int off = 1; off < 32; off <<= 1) {
                int tmp = __shfl_up_sync(0xffffffffu, ss, off);
                if (lane2 >= off) ss += tmp;
            }
            if (lane2 == 31) ws2[w2] = ss;
        }
        __syncthreads();
        if (t == 0) {
            int a = 0;
            #pragma unroll
            for (int k = 0; k < 4; k++) { int tmp = ws2[k]; ws2[k] = a; a += tmp; }
            g_scan_done = 0;   // reset for next invocation (determinism)
        }
        __syncthreads();
        if (t < 128 && t < NBLK) g_blocksum[t] = ss + ws2[t >> 5] - vv;  // exclusive base
    }
}

// scan stage 3: per-block inclusive scan + block base -> offsets; reset cursor
__global__ void scan3_kernel() {
    __shared__ int wsum[16];
    int b = blockIdx.x, t = threadIdx.x;
    int lane = t & 31, w = t >> 5;
    int i = b * SCAN_B + t;
    int v = (i < NN) ? g_counts[i] : 0;
    int s = v;
    #pragma unroll
    for (int off = 1; off < 32; off <<= 1) {
        int tmp = __shfl_up_sync(0xffffffffu, s, off);
        if (lane >= off) s += tmp;
    }
    if (lane == 31) wsum[w] = s;
    __syncthreads();
    if (w == 0 && lane < 16) {
        int ws_ = wsum[lane];
        #pragma unroll
        for (int off = 1; off < 16; off <<= 1) {
            int tmp = __shfl_up_sync(0x0000ffffu, ws_, off);
            if (lane >= off) ws_ += tmp;
        }
        wsum[lane] = ws_;
    }
    __syncthreads();
    int prefix = (w > 0) ? wsum[w - 1] : 0;
    int incl = s + prefix + g_blocksum[b];
    if (i < NN) {
        g_offsets[i + 1] = incl;
        g_cursor[i] = 0;
    }
    if (b == 0 && t == 0) g_offsets[0] = 0;
}

__global__ void scatter_kernel(const int* __restrict__ src, const int* __restrict__ dst) {
    int e = blockIdx.x * blockDim.x + threadIdx.x;
    if (e < EE) {
        int d = dst[e];
        int p = g_offsets[d] + atomicAdd(&g_cursor[d], 1);
        g_csr_src[p] = src[e];
    }
}

// ---------------- tf32 tensor-core GEMM + fused el/er + half-z store ----------------
__device__ __forceinline__ float to_tf32(float x) {
    uint32_t u;
    asm("cvt.rna.tf32.f32 %0, %1;" : "=r"(u) : "f"(x));
    return __uint_as_float(u);
}

__device__ __forceinline__ void mma_tf32(float c[4], const uint32_t a[4], const uint32_t b[2]) {
    asm volatile(
        "mma.sync.aligned.m16n8k8.row.col.f32.tf32.tf32.f32 "
        "{%0,%1,%2,%3}, {%4,%5,%6,%7}, {%8,%9}, {%0,%1,%2,%3};"
        : "+f"(c[0]), "+f"(c[1]), "+f"(c[2]), "+f"(c[3])
        : "r"(a[0]), "r"(a[1]), "r"(a[2]), "r"(a[3]), "r"(b[0]), "r"(b[1]));
}

// BM=128, BN=128, BK=32, 256 threads = 8 warps (4 m x 2 n). Warp tile 32x64.
__global__ void __launch_bounds__(256)
gemm_kernel(const float* __restrict__ x, const float* __restrict__ W,
            const float* __restrict__ attn_l, const float* __restrict__ attn_r) {
    __shared__ float As[128][36];
    __shared__ float Bs[128][36];

    const int g = blockIdx.y;                       // 0 -> W[1] (u), 1 -> W[2] (c)
    const float* Wg = W + (size_t)(g + 1) * HF * INF_;
    const int row0 = blockIdx.x * 128;
    const int t = threadIdx.x;
    const int lane = t & 31, wid = t >> 5;
    const int warp_m = wid >> 1, warp_n = wid & 1;

    float c[2][8][4];
    #pragma unroll
    for (int mi = 0; mi < 2; mi++)
        #pragma unroll
        for (int ni = 0; ni < 8; ni++)
            #pragma unroll
            for (int q = 0; q < 4; q++) c[mi][ni][q] = 0.0f;

    for (int k0 = 0; k0 < INF_; k0 += 32) {
        #pragma unroll
        for (int r = 0; r < 4; r++) {
            int id = t + 256 * r;
            int row = id >> 3;
            int kv = (id & 7) << 2;
            float4 v = make_float4(0.f, 0.f, 0.f, 0.f);
            int gr = row0 + row;
            if (gr < NN) v = *(const float4*)(x + (size_t)gr * INF_ + k0 + kv);
            As[row][kv + 0] = to_tf32(v.x);
            As[row][kv + 1] = to_tf32(v.y);
            As[row][kv + 2] = to_tf32(v.z);
            As[row][kv + 3] = to_tf32(v.w);
            float4 w4 = *(const float4*)(Wg + row * INF_ + k0 + kv);
            Bs[row][kv + 0] = to_tf32(w4.x);
            Bs[row][kv + 1] = to_tf32(w4.y);
            Bs[row][kv + 2] = to_tf32(w4.z);
            Bs[row][kv + 3] = to_tf32(w4.w);
        }
        __syncthreads();

        #pragma unroll
        for (int kk = 0; kk < 32; kk += 8) {
            uint32_t af[2][4], bf[8][2];
            const int ac = kk + (lane & 3);
            #pragma unroll
            for (int mi = 0; mi < 2; mi++) {
                int ar = warp_m * 32 + mi * 16 + (lane >> 2);
                af[mi][0] = __float_as_uint(As[ar][ac]);
                af[mi][1] = __float_as_uint(As[ar + 8][ac]);
                af[mi][2] = __float_as_uint(As[ar][ac + 4]);
                af[mi][3] = __float_as_uint(As[ar + 8][ac + 4]);
            }
            #pragma unroll
            for (int ni = 0; ni < 8; ni++) {
                int br = warp_n * 64 + ni * 8 + (lane >> 2);
                bf[ni][0] = __float_as_uint(Bs[br][ac]);
                bf[ni][1] = __float_as_uint(Bs[br][ac + 4]);
            }
            #pragma unroll
            for (int mi = 0; mi < 2; mi++)
                #pragma unroll
                for (int ni = 0; ni < 8; ni++)
                    mma_tf32(c[mi][ni], af[mi], bf[ni]);
        }
        __syncthreads();
    }

    // epilogue: store half z + compute el/er (head = warp_n) via quad reduction
    const float* al = attn_l + (g + 1) * HF;
    const float* ar = attn_r + (g + 1) * HF;
    #pragma unroll
    for (int mi = 0; mi < 2; mi++) {
        #pragma unroll
        for (int half = 0; half < 2; half++) {
            int rr = row0 + warp_m * 32 + mi * 16 + (lane >> 2) + half * 8;
            float elp = 0.f, erp = 0.f;
            if (rr < NN) {
                __half* zp = g_zh + ((size_t)g * NN + rr) * HF;
                #pragma unroll
                for (int ni = 0; ni < 8; ni++) {
                    int cc = warp_n * 64 + ni * 8 + (lane & 3) * 2;
                    float cx = half ? c[mi][ni][2] : c[mi][ni][0];
                    float cy = half ? c[mi][ni][3] : c[mi][ni][1];
                    *(half2*)(zp + cc) = __floats2half2_rn(cx, cy);
                    elp = fmaf(cx, __ldg(al + cc), fmaf(cy, __ldg(al + cc + 1), elp));
                    erp = fmaf(cx, __ldg(ar + cc), fmaf(cy, __ldg(ar + cc + 1), erp));
                }
            }
            elp += __shfl_xor_sync(0xffffffffu, elp, 1);
            elp += __shfl_xor_sync(0xffffffffu, elp, 2);
            erp += __shfl_xor_sync(0xffffffffu, erp, 1);
            erp += __shfl_xor_sync(0xffffffffu, erp, 2);
            if ((lane & 3) == 0 && rr < NN) {
                ((float*)g_el4)[(size_t)rr * 4 + g * 2 + warp_n] = elp;
                ((float*)g_er4)[(size_t)rr * 4 + g * 2 + warp_n] = erp;
            }
        }
    }
}

// ---------------- fused edge softmax-aggregate + sigmoid combine ----------------
// One warp per node, both gates. Online softmax (leaky_relu monotonic => exact).
// offsets[n]/offsets[n+1] bounds (R11 layout). Per-lane softmax partials,
// warp-reduced once. Inner j-loop software-pipelined: z loads for j+1 are
// issued before j's FMAs consume j's loads (register double-buffer, MLP=2).
__global__ void __launch_bounds__(256)
edge_final_kernel(const float* __restrict__ h,
                  const float* __restrict__ conv_bias,
                  const float* __restrict__ gate_bias,
                  float* __restrict__ out) {
    int n = (blockIdx.x * blockDim.x + threadIdx.x) >> 5;
    if (n >= NN) return;
    int lane = threadIdx.x & 31;
    int hf = lane * 4;

    int start = g_offsets[n], end = g_offsets[n + 1];

    float a00 = 0.f, a01 = 0.f, a02 = 0.f, a03 = 0.f;   // gate u (4 cols of this lane)
    float a10 = 0.f, a11 = 0.f, a12 = 0.f, a13 = 0.f;   // gate c
    float s0 = 0.f, s1 = 0.f, s2 = 0.f, s3 = 0.f;       // per-lane softmax partials

    if (start < end) {
        float4 ern = g_er4[n];
        float m0 = -1e30f, m1 = -1e30f, m2 = -1e30f, m3 = -1e30f;
        for (int base = start; base < end; base += 32) {
            int i = base + lane;
            int sid = 0;
            float e0 = -1e30f, e1 = -1e30f, e2 = -1e30f, e3 = -1e30f;
            if (i < end) {
                sid = g_csr_src[i];
                float4 els = g_el4[sid];
                e0 = els.x + ern.x; e0 = (e0 > 0.f) ? e0 : 0.2f * e0;
                e1 = els.y + ern.y; e1 = (e1 > 0.f) ? e1 : 0.2f * e1;
                e2 = els.z + ern.z; e2 = (e2 > 0.f) ? e2 : 0.2f * e2;
                e3 = els.w + ern.w; e3 = (e3 > 0.f) ? e3 : 0.2f * e3;
            }
            // batch max per component
            float b0 = e0, b1 = e1, b2 = e2, b3 = e3;
            #pragma unroll
            for (int off = 16; off; off >>= 1) {
                b0 = fmaxf(b0, __shfl_xor_sync(0xffffffffu, b0, off));
                b1 = fmaxf(b1, __shfl_xor_sync(0xffffffffu, b1, off));
                b2 = fmaxf(b2, __shfl_xor_sync(0xffffffffu, b2, off));
                b3 = fmaxf(b3, __shfl_xor_sync(0xffffffffu, b3, off));
            }
            float n0 = fmaxf(m0, b0), n1 = fmaxf(m1, b1);
            float n2 = fmaxf(m2, b2), n3 = fmaxf(m3, b3);
            float sc0 = __expf(m0 - n0), sc1 = __expf(m1 - n1);
            float sc2 = __expf(m2 - n2), sc3 = __expf(m3 - n3);
            float scA = (lane < 16) ? sc0 : sc1;
            float scB = (lane < 16) ? sc2 : sc3;
            a00 *= scA; a01 *= scA; a02 *= scA; a03 *= scA;
            a10 *= scB; a11 *= scB; a12 *= scB; a13 *= scB;
            s0 *= sc0; s1 *= sc1; s2 *= sc2; s3 *= sc3;
            m0 = n0; m1 = n1; m2 = n2; m3 = n3;

            float w0 = __expf(e0 - m0), w1 = __expf(e1 - m1);
            float w2 = __expf(e2 - m2), w3 = __expf(e3 - m3);   // OOB lanes: exp(-huge)=0
            s0 += w0; s1 += w1; s2 += w2; s3 += w3;              // per-lane, once per batch

            int cnt = min(32, end - base);

            // software-pipelined gather loop (prefetch depth 1)
            int sj = __shfl_sync(0xffffffffu, sid, 0);
            uint2 q0 = ((const uint2*)(g_zh + (size_t)sj * HF))[lane];
            uint2 q1 = ((const uint2*)(g_zh + ((size_t)NN + sj) * HF))[lane];
            for (int j = 0; j < cnt; j++) {
                uint2 nq0, nq1;
                if (j + 1 < cnt) {                 // warp-uniform branch
                    int sjn = __shfl_sync(0xffffffffu, sid, j + 1);
                    nq0 = ((const uint2*)(g_zh + (size_t)sjn * HF))[lane];
                    nq1 = ((const uint2*)(g_zh + ((size_t)NN + sjn) * HF))[lane];
                }
                float wj0 = __shfl_sync(0xffffffffu, w0, j);
                float wj1 = __shfl_sync(0xffffffffu, w1, j);
                float wj2 = __shfl_sync(0xffffffffu, w2, j);
                float wj3 = __shfl_sync(0xffffffffu, w3, j);
                float2 f00 = __half22float2(*(half2*)&q0.x);
                float2 f01 = __half22float2(*(half2*)&q0.y);
                float2 f10 = __half22float2(*(half2*)&q1.x);
                float2 f11 = __half22float2(*(half2*)&q1.y);
                float wA = (lane < 16) ? wj0 : wj1;
                float wB = (lane < 16) ? wj2 : wj3;
                a00 = fmaf(wA, f00.x, a00); a01 = fmaf(wA, f00.y, a01);
                a02 = fmaf(wA, f01.x, a02); a03 = fmaf(wA, f01.y, a03);
                a10 = fmaf(wB, f10.x, a10); a11 = fmaf(wB, f10.y, a11);
                a12 = fmaf(wB, f11.x, a12); a13 = fmaf(wB, f11.y, a13);
                q0 = nq0; q1 = nq1;
            }
        }
        // reduce per-lane softmax partials (rescaled identically -> exact)
        #pragma unroll
        for (int off = 16; off; off >>= 1) {
            s0 += __shfl_xor_sync(0xffffffffu, s0, off);
            s1 += __shfl_xor_sync(0xffffffffu, s1, off);
            s2 += __shfl_xor_sync(0xffffffffu, s2, off);
            s3 += __shfl_xor_sync(0xffffffffu, s3, off);
        }
        float invA = 1.0f / ((lane < 16) ? s0 : s1);
        float invB = 1.0f / ((lane < 16) ? s2 : s3);
        a00 *= invA; a01 *= invA; a02 *= invA; a03 *= invA;
        a10 *= invB; a11 *= invB; a12 *= invB; a13 *= invB;
    }

    // biases loaded after the hot loop to shorten live ranges
    float4 cbu = *(const float4*)(conv_bias + HF + hf);
    float4 gbu = *(const float4*)(gate_bias + HF + hf);
    float4 cbc = *(const float4*)(conv_bias + 2 * HF + hf);
    float4 gbc = *(const float4*)(gate_bias + 2 * HF + hf);
    float4 hv = *(const float4*)(h + (size_t)n * HF + hf);
    float u0 = 1.0f / (1.0f + __expf(-(a00 + cbu.x + gbu.x)));
    float u1 = 1.0f / (1.0f + __expf(-(a01 + cbu.y + gbu.y)));
    float u2 = 1.0f / (1.0f + __expf(-(a02 + cbu.z + gbu.z)));
    float u3 = 1.0f / (1.0f + __expf(-(a03 + cbu.w + gbu.w)));
    float c0 = 1.0f / (1.0f + __expf(-(a10 + cbc.x + gbc.x)));
    float c1 = 1.0f / (1.0f + __expf(-(a11 + cbc.y + gbc.y)));
    float c2 = 1.0f / (1.0f + __expf(-(a12 + cbc.z + gbc.z)));
    float c3 = 1.0f / (1.0f + __expf(-(a13 + cbc.w + gbc.w)));
    float4 o;
    o.x = u0 * hv.x + (1.0f - u0) * c0;
    o.y = u1 * hv.y + (1.0f - u1) * c1;
    o.z = u2 * hv.z + (1.0f - u2) * c2;
    o.w = u3 * hv.w + (1.0f - u3) * c3;
    *(float4*)(out + (size_t)n * HF + hf) = o;
}

// ---------------- launch ----------------
extern "C" void kernel_launch(void* const* d_in, const int* in_sizes, int n_in,
                              void* d_out, int out_size) {
    const float* x         = (const float*)d_in[0];
    const float* h         = (const float*)d_in[1];
    const float* W         = (const float*)d_in[2];
    const float* attn_l    = (const float*)d_in[3];
    const float* attn_r    = (const float*)d_in[4];
    const float* conv_bias = (const float*)d_in[5];
    const float* gate_bias = (const float*)d_in[6];
    const int*   src       = (const int*)d_in[7];
    const int*   dst       = (const int*)d_in[8];
    float* out = (float*)d_out;

    zero_kernel<<<(NN + 255) / 256, 256>>>();
    count_kernel<<<(EE + 511) / 512, 512>>>(dst);
    scan12_kernel<<<NBLK, SCAN_B>>>();
    scan3_kernel<<<NBLK, SCAN_B>>>();
    scatter_kernel<<<(EE + 511) / 512, 512>>>(src, dst);

    gemm_kernel<<<dim3((NN + 127) / 128, 2), 256>>>(x, W, attn_l, attn_r);
    edge_final_kernel<<<(NN * 32 + 255) / 256, 256>>>(h, conv_bias, gate_bias, out);
}

// round 15
// speedup vs baseline: 1.1838x; 1.0876x over previous
#include <cuda_runtime.h>
#include <cuda_fp16.h>
#include <math.h>
#include <stdint.h>

#define NN 50000
#define EE 800000
#define HF 128          // H*F = 2*64
#define INF_ 128        // IN_FEATS
#define SCAN_B 512
#define NBLK ((NN + SCAN_B - 1) / SCAN_B)   // 98

// ---------------- scratch (static device globals; no allocation) ----------------
__device__ __half g_zh[2u * NN * HF];    // half-precision z (messages), 25.6 MB
__device__ float4 g_el4[NN];             // (g0h0, g0h1, g1h0, g1h1)
__device__ float4 g_er4[NN];
__device__ int    g_csr_src[EE];
__device__ int    g_offsets[NN + 1];
__device__ int    g_counts[NN];
__device__ int    g_cursor[NN];
__device__ int    g_blocksum[NBLK];
__device__ int    g_scan_done = 0;

// ---------------- host-side stream/event resources (no device memory) ----------------
struct HostRes {
    cudaStream_t s2;
    cudaEvent_t evFork, evJoin;
    HostRes() {
        cudaStreamCreateWithFlags(&s2, cudaStreamNonBlocking);
        cudaEventCreateWithFlags(&evFork, cudaEventDisableTiming);
        cudaEventCreateWithFlags(&evJoin, cudaEventDisableTiming);
    }
};
static HostRes g_res;

// ---------------- CSR build ----------------
__global__ void zero_kernel() {
    int i = blockIdx.x * blockDim.x + threadIdx.x;
    if (i < NN) g_counts[i] = 0;
}

__global__ void count_kernel(const int* __restrict__ dst) {
    int e = blockIdx.x * blockDim.x + threadIdx.x;
    if (e < EE) atomicAdd(&g_counts[dst[e]], 1);
}

// fused scan stage 1+2: per-block sums; LAST block scans the 98 block sums.
__global__ void scan12_kernel() {
    __shared__ int wsum[16];
    __shared__ int ws2[4];
    __shared__ int is_last;
    int b = blockIdx.x, t = threadIdx.x;
    int lane = t & 31, w = t >> 5;
    int i = b * SCAN_B + t;
    int v = (i < NN) ? g_counts[i] : 0;
    #pragma unroll
    for (int off = 16; off; off >>= 1) v += __shfl_xor_sync(0xffffffffu, v, off);
    if (lane == 0) wsum[w] = v;
    __syncthreads();
    if (t == 0) {
        int s = 0;
        #pragma unroll
        for (int k = 0; k < 16; k++) s += wsum[k];
        g_blocksum[b] = s;
        __threadfence();
        int prev = atomicAdd(&g_scan_done, 1);
        is_last = (prev == gridDim.x - 1);
    }
    __syncthreads();
    if (is_last) {
        int ss = 0, vv = 0;
        if (t < 128) {
            int lane2 = t & 31, w2 = t >> 5;
            vv = (t < NBLK) ? g_blocksum[t] : 0;
            ss = vv;
            #pragma unroll
            for (int off = 1; off < 32; off <<= 1) {
                int tmp = __shfl_up_sync(0xffffffffu, ss, off);
                if (lane2 >= off) ss += tmp;
            }
            if (lane2 == 31) ws2[w2] = ss;
        }
        __syncthreads();
        if (t == 0) {
            int a = 0;
            #pragma unroll
            for (int k = 0; k < 4; k++) { int tmp = ws2[k]; ws2[k] = a; a += tmp; }
            g_scan_done = 0;   // reset for next invocation (determinism)
        }
        __syncthreads();
        if (t < 128 && t < NBLK) g_blocksum[t] = ss + ws2[t >> 5] - vv;  // exclusive base
    }
}

// scan stage 3: per-block inclusive scan + block base -> offsets; reset cursor
__global__ void scan3_kernel() {
    __shared__ int wsum[16];
    int b = blockIdx.x, t = threadIdx.x;
    int lane = t & 31, w = t >> 5;
    int i = b * SCAN_B + t;
    int v = (i < NN) ? g_counts[i] : 0;
    int s = v;
    #pragma unroll
    for (int off = 1; off < 32; off <<= 1) {
        int tmp = __shfl_up_sync(0xffffffffu, s, off);
        if (lane >= off) s += tmp;
    }
    if (lane == 31) wsum[w] = s;
    __syncthreads();
    if (w == 0 && lane < 16) {
        int ws_ = wsum[lane];
        #pragma unroll
        for (int off = 1; off < 16; off <<= 1) {
            int tmp = __shfl_up_sync(0x0000ffffu, ws_, off);
            if (lane >= off) ws_ += tmp;
        }
        wsum[lane] = ws_;
    }
    __syncthreads();
    int prefix = (w > 0) ? wsum[w - 1] : 0;
    int incl = s + prefix + g_blocksum[b];
    if (i < NN) {
        g_offsets[i + 1] = incl;
        g_cursor[i] = 0;
    }
    if (b == 0 && t == 0) g_offsets[0] = 0;
}

__global__ void scatter_kernel(const int* __restrict__ src, const int* __restrict__ dst) {
    int e = blockIdx.x * blockDim.x + threadIdx.x;
    if (e < EE) {
        int d = dst[e];
        int p = g_offsets[d] + atomicAdd(&g_cursor[d], 1);
        g_csr_src[p] = src[e];
    }
}

// ---------------- tf32 tensor-core GEMM + fused el/er + half-z store ----------------
__device__ __forceinline__ float to_tf32(float x) {
    uint32_t u;
    asm("cvt.rna.tf32.f32 %0, %1;" : "=r"(u) : "f"(x));
    return __uint_as_float(u);
}

__device__ __forceinline__ void mma_tf32(float c[4], const uint32_t a[4], const uint32_t b[2]) {
    asm volatile(
        "mma.sync.aligned.m16n8k8.row.col.f32.tf32.tf32.f32 "
        "{%0,%1,%2,%3}, {%4,%5,%6,%7}, {%8,%9}, {%0,%1,%2,%3};"
        : "+f"(c[0]), "+f"(c[1]), "+f"(c[2]), "+f"(c[3])
        : "r"(a[0]), "r"(a[1]), "r"(a[2]), "r"(a[3]), "r"(b[0]), "r"(b[1]));
}

// BM=128, BN=128, BK=32, 256 threads = 8 warps (4 m x 2 n). Warp tile 32x64.
__global__ void __launch_bounds__(256)
gemm_kernel(const float* __restrict__ x, const float* __restrict__ W,
            const float* __restrict__ attn_l, const float* __restrict__ attn_r) {
    __shared__ float As[128][36];
    __shared__ float Bs[128][36];

    const int g = blockIdx.y;                       // 0 -> W[1] (u), 1 -> W[2] (c)
    const float* Wg = W + (size_t)(g + 1) * HF * INF_;
    const int row0 = blockIdx.x * 128;
    const int t = threadIdx.x;
    const int lane = t & 31, wid = t >> 5;
    const int warp_m = wid >> 1, warp_n = wid & 1;

    float c[2][8][4];
    #pragma unroll
    for (int mi = 0; mi < 2; mi++)
        #pragma unroll
        for (int ni = 0; ni < 8; ni++)
            #pragma unroll
            for (int q = 0; q < 4; q++) c[mi][ni][q] = 0.0f;

    for (int k0 = 0; k0 < INF_; k0 += 32) {
        #pragma unroll
        for (int r = 0; r < 4; r++) {
            int id = t + 256 * r;
            int row = id >> 3;
            int kv = (id & 7) << 2;
            float4 v = make_float4(0.f, 0.f, 0.f, 0.f);
            int gr = row0 + row;
            if (gr < NN) v = *(const float4*)(x + (size_t)gr * INF_ + k0 + kv);
            As[row][kv + 0] = to_tf32(v.x);
            As[row][kv + 1] = to_tf32(v.y);
            As[row][kv + 2] = to_tf32(v.z);
            As[row][kv + 3] = to_tf32(v.w);
            float4 w4 = *(const float4*)(Wg + row * INF_ + k0 + kv);
            Bs[row][kv + 0] = to_tf32(w4.x);
            Bs[row][kv + 1] = to_tf32(w4.y);
            Bs[row][kv + 2] = to_tf32(w4.z);
            Bs[row][kv + 3] = to_tf32(w4.w);
        }
        __syncthreads();

        #pragma unroll
        for (int kk = 0; kk < 32; kk += 8) {
            uint32_t af[2][4], bf[8][2];
            const int ac = kk + (lane & 3);
            #pragma unroll
            for (int mi = 0; mi < 2; mi++) {
                int ar = warp_m * 32 + mi * 16 + (lane >> 2);
                af[mi][0] = __float_as_uint(As[ar][ac]);
                af[mi][1] = __float_as_uint(As[ar + 8][ac]);
                af[mi][2] = __float_as_uint(As[ar][ac + 4]);
                af[mi][3] = __float_as_uint(As[ar + 8][ac + 4]);
            }
            #pragma unroll
            for (int ni = 0; ni < 8; ni++) {
                int br = warp_n * 64 + ni * 8 + (lane >> 2);
                bf[ni][0] = __float_as_uint(Bs[br][ac]);
                bf[ni][1] = __float_as_uint(Bs[br][ac + 4]);
            }
            #pragma unroll
            for (int mi = 0; mi < 2; mi++)
                #pragma unroll
                for (int ni = 0; ni < 8; ni++)
                    mma_tf32(c[mi][ni], af[mi], bf[ni]);
        }
        __syncthreads();
    }

    // epilogue: store half z + compute el/er (head = warp_n) via quad reduction
    const float* al = attn_l + (g + 1) * HF;
    const float* ar = attn_r + (g + 1) * HF;
    #pragma unroll
    for (int mi = 0; mi < 2; mi++) {
        #pragma unroll
        for (int half = 0; half < 2; half++) {
            int rr = row0 + warp_m * 32 + mi * 16 + (lane >> 2) + half * 8;
            float elp = 0.f, erp = 0.f;
            if (rr < NN) {
                __half* zp = g_zh + ((size_t)g * NN + rr) * HF;
                #pragma unroll
                for (int ni = 0; ni < 8; ni++) {
                    int cc = warp_n * 64 + ni * 8 + (lane & 3) * 2;
                    float cx = half ? c[mi][ni][2] : c[mi][ni][0];
                    float cy = half ? c[mi][ni][3] : c[mi][ni][1];
                    *(half2*)(zp + cc) = __floats2half2_rn(cx, cy);
                    elp = fmaf(cx, __ldg(al + cc), fmaf(cy, __ldg(al + cc + 1), elp));
                    erp = fmaf(cx, __ldg(ar + cc), fmaf(cy, __ldg(ar + cc + 1), erp));
                }
            }
            elp += __shfl_xor_sync(0xffffffffu, elp, 1);
            elp += __shfl_xor_sync(0xffffffffu, elp, 2);
            erp += __shfl_xor_sync(0xffffffffu, erp, 1);
            erp += __shfl_xor_sync(0xffffffffu, erp, 2);
            if ((lane & 3) == 0 && rr < NN) {
                ((float*)g_el4)[(size_t)rr * 4 + g * 2 + warp_n] = elp;
                ((float*)g_er4)[(size_t)rr * 4 + g * 2 + warp_n] = erp;
            }
        }
    }
}

// ---------------- fused edge softmax-aggregate + sigmoid combine ----------------
// One warp per node, both gates. Online softmax (leaky_relu monotonic => exact).
// Per-lane softmax partials, warp-reduced once. j-loop software-pipelined.
__global__ void __launch_bounds__(256)
edge_final_kernel(const float* __restrict__ h,
                  const float* __restrict__ conv_bias,
                  const float* __restrict__ gate_bias,
                  float* __restrict__ out) {
    int n = (blockIdx.x * blockDim.x + threadIdx.x) >> 5;
    if (n >= NN) return;
    int lane = threadIdx.x & 31;
    int hf = lane * 4;

    int start = g_offsets[n], end = g_offsets[n + 1];

    float a00 = 0.f, a01 = 0.f, a02 = 0.f, a03 = 0.f;   // gate u (4 cols of this lane)
    float a10 = 0.f, a11 = 0.f, a12 = 0.f, a13 = 0.f;   // gate c
    float s0 = 0.f, s1 = 0.f, s2 = 0.f, s3 = 0.f;       // per-lane softmax partials

    if (start < end) {
        float4 ern = g_er4[n];
        float m0 = -1e30f, m1 = -1e30f, m2 = -1e30f, m3 = -1e30f;
        for (int base = start; base < end; base += 32) {
            int i = base + lane;
            int sid = 0;
            float e0 = -1e30f, e1 = -1e30f, e2 = -1e30f, e3 = -1e30f;
            if (i < end) {
                sid = g_csr_src[i];
                float4 els = g_el4[sid];
                e0 = els.x + ern.x; e0 = (e0 > 0.f) ? e0 : 0.2f * e0;
                e1 = els.y + ern.y; e1 = (e1 > 0.f) ? e1 : 0.2f * e1;
                e2 = els.z + ern.z; e2 = (e2 > 0.f) ? e2 : 0.2f * e2;
                e3 = els.w + ern.w; e3 = (e3 > 0.f) ? e3 : 0.2f * e3;
            }
            // batch max per component
            float b0 = e0, b1 = e1, b2 = e2, b3 = e3;
            #pragma unroll
            for (int off = 16; off; off >>= 1) {
                b0 = fmaxf(b0, __shfl_xor_sync(0xffffffffu, b0, off));
                b1 = fmaxf(b1, __shfl_xor_sync(0xffffffffu, b1, off));
                b2 = fmaxf(b2, __shfl_xor_sync(0xffffffffu, b2, off));
                b3 = fmaxf(b3, __shfl_xor_sync(0xffffffffu, b3, off));
            }
            float n0 = fmaxf(m0, b0), n1 = fmaxf(m1, b1);
            float n2 = fmaxf(m2, b2), n3 = fmaxf(m3, b3);
            float sc0 = __expf(m0 - n0), sc1 = __expf(m1 - n1);
            float sc2 = __expf(m2 - n2), sc3 = __expf(m3 - n3);
            float scA = (lane < 16) ? sc0 : sc1;
            float scB = (lane < 16) ? sc2 : sc3;
            a00 *= scA; a01 *= scA; a02 *= scA; a03 *= scA;
            a10 *= scB; a11 *= scB; a12 *= scB; a13 *= scB;
            s0 *= sc0; s1 *= sc1; s2 *= sc2; s3 *= sc3;
            m0 = n0; m1 = n1; m2 = n2; m3 = n3;

            float w0 = __expf(e0 - m0), w1 = __expf(e1 - m1);
            float w2 = __expf(e2 - m2), w3 = __expf(e3 - m3);   // OOB lanes: exp(-huge)=0
            s0 += w0; s1 += w1; s2 += w2; s3 += w3;              // per-lane, once per batch

            int cnt = min(32, end - base);

            // software-pipelined gather loop (prefetch depth 1)
            int sj = __shfl_sync(0xffffffffu, sid, 0);
            uint2 q0 = ((const uint2*)(g_zh + (size_t)sj * HF))[lane];
            uint2 q1 = ((const uint2*)(g_zh + ((size_t)NN + sj) * HF))[lane];
            for (int j = 0; j < cnt; j++) {
                uint2 nq0, nq1;
                if (j + 1 < cnt) {                 // warp-uniform branch
                    int sjn = __shfl_sync(0xffffffffu, sid, j + 1);
                    nq0 = ((const uint2*)(g_zh + (size_t)sjn * HF))[lane];
                    nq1 = ((const uint2*)(g_zh + ((size_t)NN + sjn) * HF))[lane];
                }
                float wj0 = __shfl_sync(0xffffffffu, w0, j);
                float wj1 = __shfl_sync(0xffffffffu, w1, j);
                float wj2 = __shfl_sync(0xffffffffu, w2, j);
                float wj3 = __shfl_sync(0xffffffffu, w3, j);
                float2 f00 = __half22float2(*(half2*)&q0.x);
                float2 f01 = __half22float2(*(half2*)&q0.y);
                float2 f10 = __half22float2(*(half2*)&q1.x);
                float2 f11 = __half22float2(*(half2*)&q1.y);
                float wA = (lane < 16) ? wj0 : wj1;
                float wB = (lane < 16) ? wj2 : wj3;
                a00 = fmaf(wA, f00.x, a00); a01 = fmaf(wA, f00.y, a01);
                a02 = fmaf(wA, f01.x, a02); a03 = fmaf(wA, f01.y, a03);
                a10 = fmaf(wB, f10.x, a10); a11 = fmaf(wB, f10.y, a11);
                a12 = fmaf(wB, f11.x, a12); a13 = fmaf(wB, f11.y, a13);
                q0 = nq0; q1 = nq1;
            }
        }
        // reduce per-lane softmax partials (rescaled identically -> exact)
        #pragma unroll
        for (int off = 16; off; off >>= 1) {
            s0 += __shfl_xor_sync(0xffffffffu, s0, off);
            s1 += __shfl_xor_sync(0xffffffffu, s1, off);
            s2 += __shfl_xor_sync(0xffffffffu, s2, off);
            s3 += __shfl_xor_sync(0xffffffffu, s3, off);
        }
        float invA = 1.0f / ((lane < 16) ? s0 : s1);
        float invB = 1.0f / ((lane < 16) ? s2 : s3);
        a00 *= invA; a01 *= invA; a02 *= invA; a03 *= invA;
        a10 *= invB; a11 *= invB; a12 *= invB; a13 *= invB;
    }

    // biases loaded after the hot loop to shorten live ranges
    float4 cbu = *(const float4*)(conv_bias + HF + hf);
    float4 gbu = *(const float4*)(gate_bias + HF + hf);
    float4 cbc = *(const float4*)(conv_bias + 2 * HF + hf);
    float4 gbc = *(const float4*)(gate_bias + 2 * HF + hf);
    float4 hv = *(const float4*)(h + (size_t)n * HF + hf);
    float u0 = 1.0f / (1.0f + __expf(-(a00 + cbu.x + gbu.x)));
    float u1 = 1.0f / (1.0f + __expf(-(a01 + cbu.y + gbu.y)));
    float u2 = 1.0f / (1.0f + __expf(-(a02 + cbu.z + gbu.z)));
    float u3 = 1.0f / (1.0f + __expf(-(a03 + cbu.w + gbu.w)));
    float c0 = 1.0f / (1.0f + __expf(-(a10 + cbc.x + gbc.x)));
    float c1 = 1.0f / (1.0f + __expf(-(a11 + cbc.y + gbc.y)));
    float c2 = 1.0f / (1.0f + __expf(-(a12 + cbc.z + gbc.z)));
    float c3 = 1.0f / (1.0f + __expf(-(a13 + cbc.w + gbc.w)));
    float4 o;
    o.x = u0 * hv.x + (1.0f - u0) * c0;
    o.y = u1 * hv.y + (1.0f - u1) * c1;
    o.z = u2 * hv.z + (1.0f - u2) * c2;
    o.w = u3 * hv.w + (1.0f - u3) * c3;
    *(float4*)(out + (size_t)n * HF + hf) = o;
}

// ---------------- launch: CSR chain on s2 ∥ GEMM on capture stream ----------------
extern "C" void kernel_launch(void* const* d_in, const int* in_sizes, int n_in,
                              void* d_out, int out_size) {
    const float* x         = (const float*)d_in[0];
    const float* h         = (const float*)d_in[1];
    const float* W         = (const float*)d_in[2];
    const float* attn_l    = (const float*)d_in[3];
    const float* attn_r    = (const float*)d_in[4];
    const float* conv_bias = (const float*)d_in[5];
    const float* gate_bias = (const float*)d_in[6];
    const int*   src       = (const int*)d_in[7];
    const int*   dst       = (const int*)d_in[8];
    float* out = (float*)d_out;

    cudaStream_t s2 = g_res.s2;

    // fork: CSR build on s2 (independent of GEMM until edge_final)
    cudaEventRecord(g_res.evFork, 0);
    cudaStreamWaitEvent(s2, g_res.evFork, 0);

    zero_kernel<<<(NN + 255) / 256, 256, 0, s2>>>();
    count_kernel<<<(EE + 511) / 512, 512, 0, s2>>>(dst);
    scan12_kernel<<<NBLK, SCAN_B, 0, s2>>>();
    scan3_kernel<<<NBLK, SCAN_B, 0, s2>>>();
    scatter_kernel<<<(EE + 511) / 512, 512, 0, s2>>>(src, dst);

    // GEMM (+ fused el/er) on the capture stream, concurrent with CSR build
    gemm_kernel<<<dim3((NN + 127) / 128, 2), 256>>>(x, W, attn_l, attn_r);

    // join: edge_final needs both
    cudaEventRecord(g_res.evJoin, s2);
    cudaStreamWaitEvent(0, g_res.evJoin, 0);

    edge_final_kernel<<<(NN * 32 + 255) / 256, 256>>>(h, conv_bias, gate_bias, out);
}